// round 10
// baseline (speedup 1.0000x reference)
#include <cuda_runtime.h>
#include <cuda_fp16.h>
#include <cstdint>
#include <cmath>

#define PP 512
#define CC 65536
#define TILE_C 32
#define NTHREADS 256

// A: softmaxed, fp16-rounded, packed in m16n8k16 A-fragment order:
//   g_A[(((mt*32 + k16)*32 + lane)*4 + regidx]  (uint32 = fp16x2)
__device__ uint32_t g_A[PP * PP / 2];

// ---------------------------------------------------------------------------
// Kernel 1: softmax rows of rule_weights[r,0,:] -> g_A (fp16x2, frag-packed)
// ---------------------------------------------------------------------------
__global__ void ilp_softmax_kernel(const float* __restrict__ rw) {
    const int r = blockIdx.x;
    const int tid = threadIdx.x;
    const float* wrow = rw + r * PP;

    __shared__ float wbuf[8];
    __shared__ float s_mx, s_inv;

    float2 v = *(const float2*)&wrow[2 * tid];

    float m = fmaxf(v.x, v.y);
    #pragma unroll
    for (int o = 16; o; o >>= 1) m = fmaxf(m, __shfl_xor_sync(0xffffffffu, m, o));
    if ((tid & 31) == 0) wbuf[tid >> 5] = m;
    __syncthreads();
    if (tid == 0) {
        float mm = wbuf[0];
        #pragma unroll
        for (int w = 1; w < 8; ++w) mm = fmaxf(mm, wbuf[w]);
        s_mx = mm;
    }
    __syncthreads();

    float e0 = expf(v.x - s_mx);
    float e1 = expf(v.y - s_mx);
    float s = e0 + e1;
    #pragma unroll
    for (int o = 16; o; o >>= 1) s += __shfl_xor_sync(0xffffffffu, s, o);
    if ((tid & 31) == 0) wbuf[tid >> 5] = s;
    __syncthreads();
    if (tid == 0) {
        float ss = 0.f;
        #pragma unroll
        for (int w = 0; w < 8; ++w) ss += wbuf[w];
        s_inv = 1.0f / ss;
    }
    __syncthreads();

    const int mt     = r >> 4;
    const int row_in = r & 15;
    const int k16    = tid >> 3;
    const int lane   = ((row_in & 7) << 2) | (tid & 3);
    const int regidx = ((row_in >> 3) & 1) | (((tid >> 2) & 1) << 1);

    __half2 h2 = __floats2half2_rn(e0 * s_inv, e1 * s_inv);
    g_A[(((mt * 32 + k16) * 32 + lane) << 2) | regidx] = *(const uint32_t*)&h2;
}

// ---------------------------------------------------------------------------
// Kernel 2: fused forward chaining via mma.sync m16n8k16 f16 (fp32 accum).
//   CTA: 32 columns, xs 32KB fp16 (READ-ONLY) -> 2 CTAs/SM.
//   Warp w: rows [64w,64w+64): 4 m-tiles x 4 n-tiles -> 64 fp32 accumulators.
//   Running col-max M folded into B fragments at consume time (hmax2),
//   so no per-iteration xs rewrite pass and no extra barrier.
// ---------------------------------------------------------------------------

__device__ __forceinline__ uint32_t hmax2u(uint32_t a, uint32_t b) {
    __half2 r = __hmax2(*(__half2*)&a, *(__half2*)&b);
    return *(uint32_t*)&r;
}

#define MMA_STEP(ap, bf, Mh)                                                   \
    do {                                                                       \
        _Pragma("unroll")                                                      \
        for (int mt = 0; mt < 4; ++mt) {                                       \
            const uint32_t a0 = (ap)[mt].x, a1 = (ap)[mt].y;                   \
            const uint32_t a2 = (ap)[mt].z, a3 = (ap)[mt].w;                   \
            _Pragma("unroll")                                                  \
            for (int nt = 0; nt < 4; ++nt) {                                   \
                const int j = ((nt >> 1) << 1) | (nt & 1);                     \
                uint32_t b0 = (nt & 1) ? ((nt >> 1) ? (bf)[1].z : (bf)[0].z)   \
                                       : ((nt >> 1) ? (bf)[1].x : (bf)[0].x);  \
                uint32_t b1 = (nt & 1) ? ((nt >> 1) ? (bf)[1].w : (bf)[0].w)   \
                                       : ((nt >> 1) ? (bf)[1].y : (bf)[0].y);  \
                b0 = hmax2u(b0, (Mh)[j]);                                      \
                b1 = hmax2u(b1, (Mh)[j]);                                      \
                asm volatile(                                                  \
                    "mma.sync.aligned.m16n8k16.row.col.f32.f16.f16.f32 "      \
                    "{%0,%1,%2,%3}, {%4,%5,%6,%7}, {%8,%9}, {%0,%1,%2,%3};"   \
                    : "+f"(acc[mt][nt][0]), "+f"(acc[mt][nt][1]),              \
                      "+f"(acc[mt][nt][2]), "+f"(acc[mt][nt][3])               \
                    : "r"(a0), "r"(a1), "r"(a2), "r"(a3),                      \
                      "r"(b0), "r"(b1));                                       \
            }                                                                  \
        }                                                                      \
    } while (0)

__global__ void __launch_bounds__(NTHREADS, 2)
ilp_mma_kernel(const float* __restrict__ facts,
               const int* __restrict__ nit_ptr,
               float* __restrict__ out) {
    __shared__ __align__(16) uint32_t xs[PP * TILE_C / 2];  // 32 KB fp16
    __shared__ float s_M[TILE_C];
    __shared__ float s_red[8][TILE_C];

    const int tid  = threadIdx.x;
    const int wid  = tid >> 5;
    const int lane = tid & 31;
    const int cbase = blockIdx.x * TILE_C;

    if (tid < TILE_C) s_M[tid] = -INFINITY;

    // load f0 tile -> xs (fp16-round, B-frag pack); xs stays read-only after
    const int c4   = tid & 7;                        // float4 col group (0..7)
    const int prow = tid >> 3;                       // 0..31
    __half* xsh = (__half*)xs;
    for (int p = prow; p < PP; p += 32) {
        float4 v = *(const float4*)&facts[(size_t)p * CC + cbase + c4 * 4];
        const int k16 = p >> 4;
        const int bp  = (p >> 3) & 1;
        const int ln  = (p >> 1) & 3;
        const int hf  = p & 1;
        const float vv[4] = {v.x, v.y, v.z, v.w};
        #pragma unroll
        for (int j = 0; j < 4; ++j) {
            const int c = c4 * 4 + j;
            const int lane_d = ((c & 7) << 2) | ln;
            const int ntp = (c >> 4) & 1;
            const int q = (((c >> 3) & 1) << 1) | bp;
            xsh[((((k16 * 2 + ntp) * 32 + lane_d) << 2) | q) * 2 + hf] =
                __float2half_rn(vv[j]);
        }
    }
    __syncthreads();

    const int n_it = nit_ptr ? *nit_ptr : 3;
    // fragment base pointers (pointer-increment addressing in the k-loop)
    const uint4* Abase = (const uint4*)g_A + (size_t)wid * 4096 + lane;
    const uint4* xsb   = (const uint4*)xs + lane;
    const int crow = lane >> 2;   // column-in-group this thread consumes

    for (int it = 0; it < n_it; ++it) {
        // per-thread fp16x2-dup'd running max for the 4 column groups it uses
        uint32_t Mh[4];
        #pragma unroll
        for (int j = 0; j < 4; ++j) {
            __half2 h = __float2half2_rn(s_M[crow + 8 * j]);
            Mh[j] = *(uint32_t*)&h;
        }

        float acc[4][4][4];
        #pragma unroll
        for (int mt = 0; mt < 4; ++mt)
            #pragma unroll
            for (int nt = 0; nt < 4; ++nt)
                #pragma unroll
                for (int q = 0; q < 4; ++q) acc[mt][nt][q] = 0.f;

        uint4 apA[4], apB[4], bfA[2], bfB[2];
        #pragma unroll
        for (int mt = 0; mt < 4; ++mt) apA[mt] = Abase[mt * 1024];
        bfA[0] = xsb[0];
        bfA[1] = xsb[32];

        for (int k16 = 0; k16 < 32; k16 += 2) {
            // prefetch k16+1 operands into B buffers
            #pragma unroll
            for (int mt = 0; mt < 4; ++mt)
                apB[mt] = Abase[mt * 1024 + (k16 + 1) * 32];
            bfB[0] = xsb[(k16 + 1) * 64];
            bfB[1] = xsb[(k16 + 1) * 64 + 32];

            MMA_STEP(apA, bfA, Mh);

            // prefetch k16+2 operands into A buffers
            if (k16 + 2 < 32) {
                #pragma unroll
                for (int mt = 0; mt < 4; ++mt)
                    apA[mt] = Abase[mt * 1024 + (k16 + 2) * 32];
                bfA[0] = xsb[(k16 + 2) * 64];
                bfA[1] = xsb[(k16 + 2) * 64 + 32];
            }

            MMA_STEP(apB, bfB, Mh);
        }

        // epilogue: column max. d-frag: row=(lane>>2)(+8), col=(lane&3)*2(+1)
        #pragma unroll
        for (int nt = 0; nt < 4; ++nt) {
            float m0 = -INFINITY, m1 = -INFINITY;
            #pragma unroll
            for (int mt = 0; mt < 4; ++mt) {
                m0 = fmaxf(m0, fmaxf(acc[mt][nt][0], acc[mt][nt][2]));
                m1 = fmaxf(m1, fmaxf(acc[mt][nt][1], acc[mt][nt][3]));
            }
            #pragma unroll
            for (int o = 4; o <= 16; o <<= 1) {
                m0 = fmaxf(m0, __shfl_xor_sync(0xffffffffu, m0, o));
                m1 = fmaxf(m1, __shfl_xor_sync(0xffffffffu, m1, o));
            }
            if (lane < 4) {
                s_red[wid][nt * 8 + lane * 2 + 0] = m0;
                s_red[wid][nt * 8 + lane * 2 + 1] = m1;
            }
        }
        __syncthreads();
        if (tid < TILE_C) {
            float mm = s_M[tid];
            #pragma unroll
            for (int w = 0; w < 8; ++w) mm = fmaxf(mm, s_red[w][tid]);
            s_M[tid] = mm;
        }
        __syncthreads();
    }

    // output: max(exact f0, M_final), coalesced float4
    for (int p = prow; p < PP; p += 32) {
        float4 v = *(const float4*)&facts[(size_t)p * CC + cbase + c4 * 4];
        v.x = fmaxf(v.x, s_M[c4 * 4 + 0]);
        v.y = fmaxf(v.y, s_M[c4 * 4 + 1]);
        v.z = fmaxf(v.z, s_M[c4 * 4 + 2]);
        v.w = fmaxf(v.w, s_M[c4 * 4 + 3]);
        *(float4*)&out[(size_t)p * CC + cbase + c4 * 4] = v;
    }
}

// ---------------------------------------------------------------------------
extern "C" void kernel_launch(void* const* d_in, const int* in_sizes, int n_in,
                              void* d_out, int out_size) {
    (void)in_sizes; (void)out_size;
    const float* facts = (const float*)d_in[0];
    const float* rw    = (const float*)d_in[1];
    const int*   nit   = (n_in > 2) ? (const int*)d_in[2] : nullptr;
    float* out = (float*)d_out;

    ilp_softmax_kernel<<<PP, NTHREADS>>>(rw);
    ilp_mma_kernel<<<CC / TILE_C, NTHREADS>>>(facts, nit, out);
}

// round 11
// speedup vs baseline: 1.2344x; 1.2344x over previous
#include <cuda_runtime.h>
#include <cuda_fp16.h>
#include <cstdint>
#include <cmath>

#define PP 512
#define CC 65536
#define TILE_C 32
#define NTHREADS 256

// A: softmaxed, fp16-rounded, packed in m16n8k16 A-fragment order:
//   g_A[(((mt*32 + k16)*32 + lane)*4 + regidx]  (uint32 = fp16x2)
__device__ uint32_t g_A[PP * PP / 2];

// ---------------------------------------------------------------------------
// Kernel 1: softmax rows of rule_weights[r,0,:] -> g_A (fp16x2, frag-packed)
// ---------------------------------------------------------------------------
__global__ void ilp_softmax_kernel(const float* __restrict__ rw) {
    const int r = blockIdx.x;
    const int tid = threadIdx.x;
    const float* wrow = rw + r * PP;

    __shared__ float wbuf[8];
    __shared__ float s_mx, s_inv;

    float2 v = *(const float2*)&wrow[2 * tid];

    float m = fmaxf(v.x, v.y);
    #pragma unroll
    for (int o = 16; o; o >>= 1) m = fmaxf(m, __shfl_xor_sync(0xffffffffu, m, o));
    if ((tid & 31) == 0) wbuf[tid >> 5] = m;
    __syncthreads();
    if (tid == 0) {
        float mm = wbuf[0];
        #pragma unroll
        for (int w = 1; w < 8; ++w) mm = fmaxf(mm, wbuf[w]);
        s_mx = mm;
    }
    __syncthreads();

    float e0 = expf(v.x - s_mx);
    float e1 = expf(v.y - s_mx);
    float s = e0 + e1;
    #pragma unroll
    for (int o = 16; o; o >>= 1) s += __shfl_xor_sync(0xffffffffu, s, o);
    if ((tid & 31) == 0) wbuf[tid >> 5] = s;
    __syncthreads();
    if (tid == 0) {
        float ss = 0.f;
        #pragma unroll
        for (int w = 0; w < 8; ++w) ss += wbuf[w];
        s_inv = 1.0f / ss;
    }
    __syncthreads();

    const int mt     = r >> 4;
    const int row_in = r & 15;
    const int k16    = tid >> 3;
    const int lane   = ((row_in & 7) << 2) | (tid & 3);
    const int regidx = ((row_in >> 3) & 1) | (((tid >> 2) & 1) << 1);

    __half2 h2 = __floats2half2_rn(e0 * s_inv, e1 * s_inv);
    g_A[(((mt * 32 + k16) * 32 + lane) << 2) | regidx] = *(const uint32_t*)&h2;
}

// ---------------------------------------------------------------------------
// Kernel 2: fused forward chaining via mma.sync m16n8k16 f16 (fp32 accum).
//   CTA: 32 columns, xs 32KB fp16 (READ-ONLY) -> 2 CTAs/SM.
//   Warp w: rows [64w,64w+64): 4 m-tiles x 4 n-tiles -> 64 fp32 accumulators.
//   Running col-max M folded into B fragments ONCE AT LOAD TIME (8 hmax2
//   per k16 step), so no per-iteration xs rewrite and no redundant ALU work.
// ---------------------------------------------------------------------------

__device__ __forceinline__ uint32_t hmax2u(uint32_t a, uint32_t b) {
    __half2 r = __hmax2(*(__half2*)&a, *(__half2*)&b);
    return *(uint32_t*)&r;
}

__global__ void __launch_bounds__(NTHREADS, 2)
ilp_mma_kernel(const float* __restrict__ facts,
               const int* __restrict__ nit_ptr,
               float* __restrict__ out) {
    __shared__ __align__(16) uint32_t xs[PP * TILE_C / 2];  // 32 KB fp16
    __shared__ float s_M[TILE_C];
    __shared__ float s_red[8][TILE_C];

    const int tid  = threadIdx.x;
    const int wid  = tid >> 5;
    const int lane = tid & 31;
    const int cbase = blockIdx.x * TILE_C;

    if (tid < TILE_C) s_M[tid] = -INFINITY;

    // load f0 tile -> xs (fp16-round, B-frag pack); xs stays read-only after
    const int c4   = tid & 7;                        // float4 col group (0..7)
    const int prow = tid >> 3;                       // 0..31
    __half* xsh = (__half*)xs;
    for (int p = prow; p < PP; p += 32) {
        float4 v = *(const float4*)&facts[(size_t)p * CC + cbase + c4 * 4];
        const int k16 = p >> 4;
        const int bp  = (p >> 3) & 1;
        const int ln  = (p >> 1) & 3;
        const int hf  = p & 1;
        const float vv[4] = {v.x, v.y, v.z, v.w};
        #pragma unroll
        for (int j = 0; j < 4; ++j) {
            const int c = c4 * 4 + j;
            const int lane_d = ((c & 7) << 2) | ln;
            const int ntp = (c >> 4) & 1;
            const int q = (((c >> 3) & 1) << 1) | bp;
            xsh[((((k16 * 2 + ntp) * 32 + lane_d) << 2) | q) * 2 + hf] =
                __float2half_rn(vv[j]);
        }
    }
    __syncthreads();

    const int n_it = nit_ptr ? *nit_ptr : 3;
    const uint4* A4  = (const uint4*)g_A;
    const uint4* xs4 = (const uint4*)xs;
    const int crow = lane >> 2;   // column-in-group this thread consumes

    for (int it = 0; it < n_it; ++it) {
        // per-thread fp16x2-dup'd running max for its 4 column groups
        uint32_t Mh[4];
        #pragma unroll
        for (int j = 0; j < 4; ++j) {
            __half2 h = __float2half2_rn(s_M[crow + 8 * j]);
            Mh[j] = *(uint32_t*)&h;
        }

        float acc[4][4][4];
        #pragma unroll
        for (int mt = 0; mt < 4; ++mt)
            #pragma unroll
            for (int nt = 0; nt < 4; ++nt)
                #pragma unroll
                for (int q = 0; q < 4; ++q) acc[mt][nt][q] = 0.f;

        uint4 ap[2][4];
        #pragma unroll
        for (int mt = 0; mt < 4; ++mt)
            ap[0][mt] = A4[(size_t)((wid * 4 + mt) * 32 + 0) * 32 + lane];

        #pragma unroll 2
        for (int k16 = 0; k16 < 32; ++k16) {
            const int cur = k16 & 1, nxt = cur ^ 1;
            if (k16 + 1 < 32) {
                #pragma unroll
                for (int mt = 0; mt < 4; ++mt)
                    ap[nxt][mt] =
                        A4[(size_t)((wid * 4 + mt) * 32 + (k16 + 1)) * 32 + lane];
            }
            uint4 bf[2];
            #pragma unroll
            for (int ntp = 0; ntp < 2; ++ntp) {
                bf[ntp] = xs4[(k16 * 2 + ntp) * 32 + lane];
                // fold running col-max once per loaded word (8 hmax2/step)
                bf[ntp].x = hmax2u(bf[ntp].x, Mh[2 * ntp + 0]);
                bf[ntp].y = hmax2u(bf[ntp].y, Mh[2 * ntp + 0]);
                bf[ntp].z = hmax2u(bf[ntp].z, Mh[2 * ntp + 1]);
                bf[ntp].w = hmax2u(bf[ntp].w, Mh[2 * ntp + 1]);
            }

            #pragma unroll
            for (int mt = 0; mt < 4; ++mt) {
                const uint32_t a0 = ap[cur][mt].x, a1 = ap[cur][mt].y;
                const uint32_t a2 = ap[cur][mt].z, a3 = ap[cur][mt].w;
                #pragma unroll
                for (int nt = 0; nt < 4; ++nt) {
                    const uint32_t b0 = (nt & 1) ? ((nt >> 1) ? bf[1].z : bf[0].z)
                                                 : ((nt >> 1) ? bf[1].x : bf[0].x);
                    const uint32_t b1 = (nt & 1) ? ((nt >> 1) ? bf[1].w : bf[0].w)
                                                 : ((nt >> 1) ? bf[1].y : bf[0].y);
                    asm volatile(
                        "mma.sync.aligned.m16n8k16.row.col.f32.f16.f16.f32 "
                        "{%0,%1,%2,%3}, {%4,%5,%6,%7}, {%8,%9}, {%0,%1,%2,%3};"
                        : "+f"(acc[mt][nt][0]), "+f"(acc[mt][nt][1]),
                          "+f"(acc[mt][nt][2]), "+f"(acc[mt][nt][3])
                        : "r"(a0), "r"(a1), "r"(a2), "r"(a3),
                          "r"(b0), "r"(b1));
                }
            }
        }

        // epilogue: column max. d-frag: row=(lane>>2)(+8), col=(lane&3)*2(+1)
        #pragma unroll
        for (int nt = 0; nt < 4; ++nt) {
            float m0 = -INFINITY, m1 = -INFINITY;
            #pragma unroll
            for (int mt = 0; mt < 4; ++mt) {
                m0 = fmaxf(m0, fmaxf(acc[mt][nt][0], acc[mt][nt][2]));
                m1 = fmaxf(m1, fmaxf(acc[mt][nt][1], acc[mt][nt][3]));
            }
            #pragma unroll
            for (int o = 4; o <= 16; o <<= 1) {
                m0 = fmaxf(m0, __shfl_xor_sync(0xffffffffu, m0, o));
                m1 = fmaxf(m1, __shfl_xor_sync(0xffffffffu, m1, o));
            }
            if (lane < 4) {
                s_red[wid][nt * 8 + lane * 2 + 0] = m0;
                s_red[wid][nt * 8 + lane * 2 + 1] = m1;
            }
        }
        __syncthreads();
        if (tid < TILE_C) {
            float mm = s_M[tid];
            #pragma unroll
            for (int w = 0; w < 8; ++w) mm = fmaxf(mm, s_red[w][tid]);
            s_M[tid] = mm;
        }
        __syncthreads();
    }

    // output: max(exact f0, M_final), coalesced float4
    for (int p = prow; p < PP; p += 32) {
        float4 v = *(const float4*)&facts[(size_t)p * CC + cbase + c4 * 4];
        v.x = fmaxf(v.x, s_M[c4 * 4 + 0]);
        v.y = fmaxf(v.y, s_M[c4 * 4 + 1]);
        v.z = fmaxf(v.z, s_M[c4 * 4 + 2]);
        v.w = fmaxf(v.w, s_M[c4 * 4 + 3]);
        *(float4*)&out[(size_t)p * CC + cbase + c4 * 4] = v;
    }
}

// ---------------------------------------------------------------------------
extern "C" void kernel_launch(void* const* d_in, const int* in_sizes, int n_in,
                              void* d_out, int out_size) {
    (void)in_sizes; (void)out_size;
    const float* facts = (const float*)d_in[0];
    const float* rw    = (const float*)d_in[1];
    const int*   nit   = (n_in > 2) ? (const int*)d_in[2] : nullptr;
    float* out = (float*)d_out;

    ilp_softmax_kernel<<<PP, NTHREADS>>>(rw);
    ilp_mma_kernel<<<CC / TILE_C, NTHREADS>>>(facts, nit, out);
}